// round 14
// baseline (speedup 1.0000x reference)
#include <cuda_runtime.h>
#include <cuda_fp16.h>
#include <stdint.h>

// ---------------- problem constants ----------------
#define CC   256
#define HWD  4096
#define NQ   65536
#define KK   1024
#define ZQ_ELEMS ((size_t)16777216)
#define MARGIN_T 1.5e-4f

// ---------------- device scratch ----------------
__device__ __align__(16) __half g_ch[KK * CC];
__device__ float  g_cbT[CC * KK];     // codebook transposed [c][k] (rescue)
__device__ float  g_cnorm[KK];
__device__ float  g_znorm[NQ];
__device__ float  g_bestd[NQ];
__device__ int    g_idx[NQ];
__device__ int    g_list[NQ];
__device__ int    g_cnt;
__device__ double g_losssum;

// ---------------- helpers ----------------
__device__ __forceinline__ uint32_t smem_u32(const void* p) {
    uint32_t a;
    asm("{ .reg .u64 t; cvta.to.shared.u64 t, %1; cvt.u32.u64 %0, t; }"
        : "=r"(a) : "l"(p));
    return a;
}
__device__ __forceinline__ void ldsm4(uint32_t* r, uint32_t addr) {
    asm volatile("ldmatrix.sync.aligned.m8n8.x4.shared.b16 {%0,%1,%2,%3}, [%4];"
        : "=r"(r[0]), "=r"(r[1]), "=r"(r[2]), "=r"(r[3]) : "r"(addr));
}
__device__ __forceinline__ void mma16816(float* d, const uint32_t* a, const uint32_t* b) {
    asm volatile("mma.sync.aligned.m16n8k16.row.col.f32.f16.f16.f32 "
        "{%0,%1,%2,%3}, {%4,%5,%6,%7}, {%8,%9}, {%0,%1,%2,%3};"
        : "+f"(d[0]), "+f"(d[1]), "+f"(d[2]), "+f"(d[3])
        : "r"(a[0]), "r"(a[1]), "r"(a[2]), "r"(a[3]), "r"(b[0]), "r"(b[1]));
}
#define CP_ASYNC16(dst, src) \
    asm volatile("cp.async.cg.shared.global [%0], [%1], 16;" :: "r"(dst), "l"(src))
#define CP_COMMIT() asm volatile("cp.async.commit_group;" ::: "memory")
#define CP_WAIT(n)  asm volatile("cp.async.wait_group %0;" :: "n"(n) : "memory")

// ---------------- codebook prep ----------------
__global__ void prep_cbA(const float* __restrict__ cb) {
    int i = blockIdx.x * 256 + threadIdx.x;
    int c = i >> 10, k = i & 1023;
    g_cbT[i] = cb[k * CC + c];
    g_ch[i] = __float2half(cb[i]);
}
__global__ void prep_cbB(const float* __restrict__ cb) {
    int k = blockIdx.x * 256 + threadIdx.x;
    const float* r = cb + (size_t)k * CC;
    float s = 0.f;
    #pragma unroll 8
    for (int c = 0; c < CC; c++) s = fmaf(r[c], r[c], s);
    g_cnorm[k] = s;
}
__global__ void zero_state() { g_losssum = 0.0; g_cnt = 0; }

// ---------------- main HMMA kernel -----------------------------------------
// fused: z load + znorm + fp16 convert + GEMM + argmin + zq write + loss part
// smem (bytes): A fp16 [0,64K); B 3x16KB stages [64K,112K); zns [112K,112.5K)
// post-loop: red/Ks alias the B region.
#define SM_BBUF 65536
#define SM_ZNS  114688
#define SM_TOT  115200

__device__ __forceinline__ void issue_chunk(int g, int tid, uint32_t sb) {
    int tile = g >> 2, sub = g & 3;
    const __half* base = g_ch + (size_t)tile * 128 * CC + sub * 64;
    uint32_t bufb = sb + SM_BBUF + (uint32_t)((g % 3) * 16384);
    #pragma unroll
    for (int p = 0; p < 4; p++) {
        int idx = tid + p * 256;
        int row = idx >> 3, ku = idx & 7;
        uint32_t dst = bufb + (uint32_t)row * 128u + (uint32_t)((ku ^ (row & 7)) << 4);
        CP_ASYNC16(dst, (const void*)(base + (size_t)row * CC + ku * 8));
    }
}

__global__ __launch_bounds__(256, 2)
void vq_tc(const float* __restrict__ z, const float* __restrict__ cb,
           float* __restrict__ out, float* __restrict__ outIdxF, int writeIdxF) {
    extern __shared__ char smem[];
    const uint32_t sb = smem_u32(smem);
    const int tid = threadIdx.x;
    const int lane = tid & 31, warp = tid >> 5;
    const int wm = warp >> 2, wn = warp & 3;
    const int g4 = lane >> 3;
    const int n0 = blockIdx.x * 128;
    const int bIdx = n0 >> 12, hw0 = n0 & 4095;

    // ---- fused prologue: load fp32 z tile, znorm (sequential-c), fp16 A ----
    {
        const float* zb = z + (size_t)bIdx * CC * HWD + hw0;
        float* Sg = (float*)(smem + SM_BBUF);          // staging 64c x 128q (32KB)
        float zacc = 0.f;
        for (int s = 0; s < 4; s++) {
            #pragma unroll
            for (int p = 0; p < 8; p++) {
                int idx = tid + p * 256;               // 0..2047 float4 units
                int c = idx >> 5, col = (idx & 31) * 4;
                *(float4*)(Sg + c * 128 + col) =
                    *(const float4*)(zb + (size_t)(s * 64 + c) * HWD + col);
            }
            __syncthreads();
            if (tid < 128) {
                #pragma unroll 8
                for (int c = 0; c < 64; c++) {
                    float v = Sg[c * 128 + tid];
                    zacc = fmaf(v, v, zacc);
                }
            }
            #pragma unroll
            for (int p = 0; p < 4; p++) {
                int u = tid + p * 256;                 // 0..1023 A-units
                int q = u & 127, kuL = u >> 7;
                union { uint4 u4; __half h[8]; } H;
                #pragma unroll
                for (int j = 0; j < 8; j++)
                    H.h[j] = __float2half(Sg[(kuL * 8 + j) * 128 + q]);
                int ku = s * 8 + kuL;
                *(uint4*)(smem + (uint32_t)q * 512u +
                          (uint32_t)((ku ^ (q & 7)) << 4)) = H.u4;
            }
            __syncthreads();
        }
        if (tid < 128) {
            ((float*)(smem + SM_ZNS))[tid] = zacc;
            g_znorm[n0 + tid] = zacc;
        }
    }
    const float* zns = (const float*)(smem + SM_ZNS);

    float s1[8], s2[8]; int k1[8];
    #pragma unroll
    for (int s = 0; s < 8; s++) { s1[s] = s2[s] = 3.4e38f; k1[s] = 0; }

    float acc[4][4][4];
    #pragma unroll
    for (int a = 0; a < 4; a++)
        #pragma unroll
        for (int b = 0; b < 4; b++)
            #pragma unroll
            for (int c = 0; c < 4; c++) acc[a][b][c] = 0.f;

    // staging reads done (barrier above); preload stages 0 and 1
    issue_chunk(0, tid, sb); CP_COMMIT();
    issue_chunk(1, tid, sb); CP_COMMIT();

    #define UPD2(s, dd, kk_) do { float _d = (dd); int _k = (kk_); \
        if (_d < s1[s]) { s2[s] = s1[s]; s1[s] = _d; k1[s] = _k; } \
        else if (_d < s2[s]) { s2[s] = _d; } } while (0)

    for (int i = 0; i < 32; i++) {
        if (i < 31) CP_WAIT(1); else CP_WAIT(0);
        __syncthreads();                      // stage i visible to all warps
        if (i + 2 < 32) { issue_chunk(i + 2, tid, sb); CP_COMMIT(); }
        const int cofs = (i & 3) * 8;         // A ku-offset of this 64-wide chunk
        const uint32_t bufb = sb + SM_BBUF + (uint32_t)((i % 3) * 16384);
        #pragma unroll
        for (int k16 = 0; k16 < 4; k16++) {
            uint32_t bfr[2][4];
            #pragma unroll
            for (int np = 0; np < 2; np++) {
                int nrow = wn * 32 + np * 16 + (g4 >> 1) * 8 + (lane & 7);
                int kuB = k16 * 2 + (g4 & 1);
                ldsm4(bfr[np], bufb + (uint32_t)nrow * 128u +
                               (uint32_t)((kuB ^ (nrow & 7)) << 4));
            }
            #pragma unroll
            for (int mt = 0; mt < 4; mt++) {
                int arow = wm * 64 + mt * 16 + (g4 & 1) * 8 + (lane & 7);
                int kuA = cofs + k16 * 2 + (g4 >> 1);
                uint32_t afr[4];
                ldsm4(afr, sb + (uint32_t)arow * 512u +
                           (uint32_t)((kuA ^ (arow & 7)) << 4));
                #pragma unroll
                for (int nt = 0; nt < 4; nt++)
                    mma16816(acc[mt][nt], afr, &bfr[nt >> 1][(nt & 1) * 2]);
            }
        }
        if ((i & 3) == 3) {
            int tile = i >> 2;
            #pragma unroll
            for (int mt = 0; mt < 4; mt++) {
                float zn0 = zns[wm * 64 + mt * 16 + (lane >> 2)];
                float zn1 = zns[wm * 64 + mt * 16 + 8 + (lane >> 2)];
                #pragma unroll
                for (int nt = 0; nt < 4; nt++) {
                    int c0 = wn * 32 + nt * 8 + (lane & 3) * 2;
                    int kg = tile * 128 + c0;
                    float cn0 = __ldg(&g_cnorm[kg]);
                    float cn1 = __ldg(&g_cnorm[kg + 1]);
                    UPD2(mt * 2,     zn0 + cn0 - 2.f * acc[mt][nt][0], kg);
                    UPD2(mt * 2,     zn0 + cn1 - 2.f * acc[mt][nt][1], kg + 1);
                    UPD2(mt * 2 + 1, zn1 + cn0 - 2.f * acc[mt][nt][2], kg);
                    UPD2(mt * 2 + 1, zn1 + cn1 - 2.f * acc[mt][nt][3], kg + 1);
                    acc[mt][nt][0] = acc[mt][nt][1] = acc[mt][nt][2] = acc[mt][nt][3] = 0.f;
                }
            }
        }
    }

    // quad merge (top-2 with k-tiebreak on best)
    #pragma unroll
    for (int s = 0; s < 8; s++) {
        #pragma unroll
        for (int off = 1; off <= 2; off <<= 1) {
            float ob1 = __shfl_xor_sync(0xffffffffu, s1[s], off);
            float ob2 = __shfl_xor_sync(0xffffffffu, s2[s], off);
            int   ok1 = __shfl_xor_sync(0xffffffffu, k1[s], off);
            if (ob1 < s1[s] || (ob1 == s1[s] && ok1 < k1[s])) {
                s2[s] = (s1[s] < ob2) ? s1[s] : ob2;
                s1[s] = ob1; k1[s] = ok1;
            } else {
                s2[s] = (s2[s] < ob1) ? s2[s] : ob1;
            }
        }
    }
    __syncthreads();                       // B stages dead; reuse as reduction
    float* rB1 = (float*)(smem + SM_BBUF);
    float* rB2 = rB1 + 512;
    int*   rK1 = (int*)(rB2 + 512);
    int*   Ks  = rK1 + 512;                // [128]
    float* lred = (float*)(Ks + 128);      // [4]
    if ((lane & 3) == 0) {
        #pragma unroll
        for (int s = 0; s < 8; s++) {
            int row = wm * 64 + (s >> 1) * 16 + (s & 1) * 8 + (lane >> 2);
            rB1[row * 4 + wn] = s1[s]; rB2[row * 4 + wn] = s2[s];
            rK1[row * 4 + wn] = k1[s];
        }
    }
    __syncthreads();
    if (tid < 128) {
        float B1 = rB1[tid * 4], B2 = rB2[tid * 4];
        int K1 = rK1[tid * 4];
        #pragma unroll
        for (int wq = 1; wq < 4; wq++) {
            float ob1 = rB1[tid * 4 + wq], ob2 = rB2[tid * 4 + wq];
            int   ok1 = rK1[tid * 4 + wq];
            if (ob1 < B1 || (ob1 == B1 && ok1 < K1)) {
                B2 = (B1 < ob2) ? B1 : ob2;
                B1 = ob1; K1 = ok1;
            } else {
                B2 = (B2 < ob1) ? B2 : ob1;
            }
        }
        int q = n0 + tid;
        g_idx[q] = K1;
        g_bestd[q] = B1;
        Ks[tid] = K1;
        if (B2 - B1 < MARGIN_T) {
            int pos = atomicAdd(&g_cnt, 1);
            g_list[pos] = q;
        }
        if (writeIdxF) outIdxF[q] = (float)K1;
        // loss partial: warp-reduce B1 (warps 0-3 hold 32 queries each)
        float ls = B1;
        #pragma unroll
        for (int o = 16; o > 0; o >>= 1) ls += __shfl_down_sync(0xffffffffu, ls, o);
        if (lane == 0) lred[warp] = ls;
    }
    __syncthreads();
    if (tid == 0)
        atomicAdd(&g_losssum, (double)(lred[0] + lred[1] + lred[2] + lred[3]));

    // ---- fused zq writer: thread owns (q = tid&127, ch = tid>>7) ----
    {
        const int q = tid & 127, ch = tid >> 7;
        const int k = Ks[q];
        const float* src = cb + (size_t)k * CC + ch;
        float* dst = out + (size_t)bIdx * (CC * HWD) + (size_t)ch * HWD + hw0 + q;
        #pragma unroll 8
        for (int e = 0; e < 128; e++)
            dst[(size_t)e * 2 * HWD] = __ldg(src + 2 * e);
    }
}

// ---------------- compacted exact fp32 rescue + fixups ----------------
__global__ void rescue_exact(const float* __restrict__ z, const float* __restrict__ cb,
                             float* __restrict__ out,
                             float* __restrict__ outIdxF, int writeIdxF) {
    __shared__ float cns[KK];
    __shared__ float As[8][256];
    __shared__ float znq[8];
    __shared__ int   qlist[8];
    __shared__ int   rewk[8];
    __shared__ float wred_d[8][8];
    __shared__ int   wred_k[8][8];
    const int t = threadIdx.x;
    const int lane = t & 31, w = t >> 5;
    for (int i = t; i < KK; i += 256) cns[i] = g_cnorm[i];

    for (int base = blockIdx.x * 8; base < g_cnt; base += gridDim.x * 8) {
        int nq = g_cnt - base; if (nq > 8) nq = 8;
        __syncthreads();
        if (t < 8) {
            int q = (t < nq) ? g_list[base + t] : -1;
            qlist[t] = q;
            znq[t] = (q >= 0) ? g_znorm[q] : 0.f;
            rewk[t] = -1;
        }
        __syncthreads();
        {
            int q = qlist[w];
            if (q >= 0) {
                int b = q >> 12, hw = q & 4095;
                const float* zb = z + (size_t)b * CC * HWD + hw;
                for (int c = lane; c < 256; c += 32) As[w][c] = zb[(size_t)c * HWD];
            }
        }
        __syncthreads();

        float acc[8][4];
        #pragma unroll
        for (int qj = 0; qj < 8; qj++)
            #pragma unroll
            for (int j = 0; j < 4; j++) acc[qj][j] = 0.f;

        const float4* cbt4 = (const float4*)g_cbT;
        for (int c = 0; c < 256; c++) {
            float4 cb4 = cbt4[c * 256 + t];
            #pragma unroll
            for (int qj = 0; qj < 8; qj++) {
                float zv = As[qj][c];
                acc[qj][0] = fmaf(zv, cb4.x, acc[qj][0]);
                acc[qj][1] = fmaf(zv, cb4.y, acc[qj][1]);
                acc[qj][2] = fmaf(zv, cb4.z, acc[qj][2]);
                acc[qj][3] = fmaf(zv, cb4.w, acc[qj][3]);
            }
        }

        #pragma unroll
        for (int qj = 0; qj < 8; qj++) {
            float bd = 3.4e38f; int bk = 0;
            #pragma unroll
            for (int j = 0; j < 4; j++) {
                int k = t * 4 + j;
                float d = (znq[qj] + cns[k]) - 2.f * acc[qj][j];
                if (d < bd) { bd = d; bk = k; }
            }
            #pragma unroll
            for (int off = 16; off > 0; off >>= 1) {
                float od = __shfl_down_sync(0xffffffffu, bd, off);
                int   ok = __shfl_down_sync(0xffffffffu, bk, off);
                if (od < bd || (od == bd && ok < bk)) { bd = od; bk = ok; }
            }
            if (lane == 0) { wred_d[qj][w] = bd; wred_k[qj][w] = bk; }
        }
        __syncthreads();
        if (t < nq) {
            float bd = wred_d[t][0]; int bk = wred_k[t][0];
            #pragma unroll
            for (int w2 = 1; w2 < 8; w2++) {
                float od = wred_d[t][w2]; int ok = wred_k[t][w2];
                if (od < bd || (od == bd && ok < bk)) { bd = od; bk = ok; }
            }
            int q = qlist[t];
            int oldk = g_idx[q];
            atomicAdd(&g_losssum, (double)(bd - g_bestd[q]));
            g_idx[q] = bk;
            g_bestd[q] = bd;
            if (bk != oldk) rewk[t] = bk;
            if (writeIdxF) outIdxF[q] = (float)bk;
        }
        __syncthreads();
        // rewrite zq rows whose index changed (one c per thread)
        for (int j = 0; j < nq; j++) {
            int bkj = rewk[j];
            if (bkj >= 0) {
                int q = qlist[j];
                int b = q >> 12, hw = q & 4095;
                out[(size_t)b * (CC * HWD) + (size_t)t * HWD + hw] =
                    __ldg(&cb[(size_t)bkj * CC + t]);
            }
        }
        __syncthreads();
    }
}

// ---------------- loss finalize ----------------
__global__ void loss_finalize(float* __restrict__ outLoss) {
    double m = g_losssum / (double)ZQ_ELEMS;
    float mf = (float)m;
    *outLoss = mf - 0.25f * mf;
}

// ---------------- launch ----------------
extern "C" void kernel_launch(void* const* d_in, const int* in_sizes, int n_in,
                              void* d_out, int out_size) {
    const float* z  = (const float*)d_in[0];
    const float* cb = (const float*)d_in[1];
    if (n_in >= 2 && in_sizes[0] == KK * CC && in_sizes[1] == (int)ZQ_ELEMS) {
        z = (const float*)d_in[1]; cb = (const float*)d_in[0];
    }
    float* out = (float*)d_out;

    cudaFuncSetAttribute(vq_tc, cudaFuncAttributeMaxDynamicSharedMemorySize, SM_TOT);

    int writeIdxF = (out_size >= (int)(ZQ_ELEMS + NQ)) ? 1 : 0;
    float* outIdxF = out + ZQ_ELEMS;

    // launch order: vq_tc must stay the 4th launch (ncu profiles launch #4)
    prep_cbA<<<1024, 256>>>(cb);                                   // 1
    prep_cbB<<<4, 256>>>(cb);                                      // 2
    zero_state<<<1, 1>>>();                                        // 3
    vq_tc<<<NQ / 128, 256, SM_TOT>>>(z, cb, out, outIdxF, writeIdxF); // 4 <- profiled
    rescue_exact<<<256, 256>>>(z, cb, out, outIdxF, writeIdxF);    // 5
    if (out_size >= (int)(ZQ_ELEMS + NQ + 1)) {
        loss_finalize<<<1, 1>>>(out + ZQ_ELEMS + NQ);              // 6
    }
}

// round 15
// speedup vs baseline: 1.1096x; 1.1096x over previous
#include <cuda_runtime.h>
#include <cuda_fp16.h>
#include <stdint.h>

// ---------------- problem constants ----------------
#define CC   256
#define HWD  4096
#define NQ   65536
#define KK   1024
#define ZQ_ELEMS ((size_t)16777216)
#define MARGIN_T 1.5e-4f

// ---------------- device scratch ----------------
__device__ __align__(16) __half g_ch[KK * CC];
__device__ float  g_cbT[CC * KK];     // codebook transposed [c][k]
__device__ float  g_cnorm[KK];
__device__ float  g_znorm[NQ];
__device__ float  g_bestd[NQ];
__device__ int    g_idx[NQ];
__device__ int    g_list[NQ];
__device__ int    g_cnt;
__device__ double g_losssum;

// ---------------- helpers ----------------
__device__ __forceinline__ uint32_t smem_u32(const void* p) {
    uint32_t a;
    asm("{ .reg .u64 t; cvta.to.shared.u64 t, %1; cvt.u32.u64 %0, t; }"
        : "=r"(a) : "l"(p));
    return a;
}
__device__ __forceinline__ void ldsm4(uint32_t* r, uint32_t addr) {
    asm volatile("ldmatrix.sync.aligned.m8n8.x4.shared.b16 {%0,%1,%2,%3}, [%4];"
        : "=r"(r[0]), "=r"(r[1]), "=r"(r[2]), "=r"(r[3]) : "r"(addr));
}
__device__ __forceinline__ void mma16816(float* d, const uint32_t* a, const uint32_t* b) {
    asm volatile("mma.sync.aligned.m16n8k16.row.col.f32.f16.f16.f32 "
        "{%0,%1,%2,%3}, {%4,%5,%6,%7}, {%8,%9}, {%0,%1,%2,%3};"
        : "+f"(d[0]), "+f"(d[1]), "+f"(d[2]), "+f"(d[3])
        : "r"(a[0]), "r"(a[1]), "r"(a[2]), "r"(a[3]), "r"(b[0]), "r"(b[1]));
}
#define CP_ASYNC16(dst, src) \
    asm volatile("cp.async.cg.shared.global [%0], [%1], 16;" :: "r"(dst), "l"(src))
#define CP_COMMIT() asm volatile("cp.async.commit_group;" ::: "memory")
#define CP_WAIT(n)  asm volatile("cp.async.wait_group %0;" :: "n"(n) : "memory")

// ---------------- codebook prep ----------------
__global__ void prep_cbA(const float* __restrict__ cb) {
    int i = blockIdx.x * 256 + threadIdx.x;
    int c = i >> 10, k = i & 1023;
    g_cbT[i] = cb[k * CC + c];
    g_ch[i] = __float2half(cb[i]);
}
__global__ void prep_cbB(const float* __restrict__ cb) {
    int k = blockIdx.x * 256 + threadIdx.x;
    const float* r = cb + (size_t)k * CC;
    float s = 0.f;
    #pragma unroll 8
    for (int c = 0; c < CC; c++) s = fmaf(r[c], r[c], s);
    g_cnorm[k] = s;
}
__global__ void zero_state() { g_losssum = 0.0; g_cnt = 0; }

// ---------------- main HMMA kernel -----------------------------------------
// fused: z load + znorm + fp16 convert + GEMM + argmin + zq write + loss part
// smem (bytes): A fp16 [0,64K); B 3x16KB stages [64K,112K); zns [112K,112.5K)
// post-loop: red/Ks alias the B region.
#define SM_BBUF 65536
#define SM_ZNS  114688
#define SM_TOT  115200

__device__ __forceinline__ void issue_chunk(int g, int tid, uint32_t sb) {
    int tile = g >> 2, sub = g & 3;
    const __half* base = g_ch + (size_t)tile * 128 * CC + sub * 64;
    uint32_t bufb = sb + SM_BBUF + (uint32_t)((g % 3) * 16384);
    #pragma unroll
    for (int p = 0; p < 4; p++) {
        int idx = tid + p * 256;
        int row = idx >> 3, ku = idx & 7;
        uint32_t dst = bufb + (uint32_t)row * 128u + (uint32_t)((ku ^ (row & 7)) << 4);
        CP_ASYNC16(dst, (const void*)(base + (size_t)row * CC + ku * 8));
    }
}

__global__ __launch_bounds__(256, 2)
void vq_tc(const float* __restrict__ z, const float* __restrict__ cb,
           float* __restrict__ out, float* __restrict__ outIdxF, int writeIdxF) {
    extern __shared__ char smem[];
    const uint32_t sb = smem_u32(smem);
    const int tid = threadIdx.x;
    const int lane = tid & 31, warp = tid >> 5;
    const int wm = warp >> 2, wn = warp & 3;
    const int g4 = lane >> 3;
    const int n0 = blockIdx.x * 128;
    const int bIdx = n0 >> 12, hw0 = n0 & 4095;

    // ---- fused prologue: load fp32 z tile, znorm (sequential-c), fp16 A ----
    {
        const float* zb = z + (size_t)bIdx * CC * HWD + hw0;
        float* Sg = (float*)(smem + SM_BBUF);          // staging 64c x 128q (32KB)
        float zacc = 0.f;
        for (int s = 0; s < 4; s++) {
            #pragma unroll
            for (int p = 0; p < 8; p++) {
                int idx = tid + p * 256;               // 0..2047 float4 units
                int c = idx >> 5, col = (idx & 31) * 4;
                *(float4*)(Sg + c * 128 + col) =
                    *(const float4*)(zb + (size_t)(s * 64 + c) * HWD + col);
            }
            __syncthreads();
            if (tid < 128) {
                #pragma unroll 8
                for (int c = 0; c < 64; c++) {
                    float v = Sg[c * 128 + tid];
                    zacc = fmaf(v, v, zacc);
                }
            }
            #pragma unroll
            for (int p = 0; p < 4; p++) {
                int u = tid + p * 256;                 // 0..1023 A-units
                int q = u & 127, kuL = u >> 7;
                union { uint4 u4; __half h[8]; } H;
                #pragma unroll
                for (int j = 0; j < 8; j++)
                    H.h[j] = __float2half(Sg[(kuL * 8 + j) * 128 + q]);
                int ku = s * 8 + kuL;
                *(uint4*)(smem + (uint32_t)q * 512u +
                          (uint32_t)((ku ^ (q & 7)) << 4)) = H.u4;
            }
            __syncthreads();
        }
        if (tid < 128) {
            ((float*)(smem + SM_ZNS))[tid] = zacc;
            g_znorm[n0 + tid] = zacc;
        }
    }
    const float* zns = (const float*)(smem + SM_ZNS);

    float s1[8], s2[8]; int k1[8];
    #pragma unroll
    for (int s = 0; s < 8; s++) { s1[s] = s2[s] = 3.4e38f; k1[s] = 0; }

    float acc[4][4][4];
    #pragma unroll
    for (int a = 0; a < 4; a++)
        #pragma unroll
        for (int b = 0; b < 4; b++)
            #pragma unroll
            for (int c = 0; c < 4; c++) acc[a][b][c] = 0.f;

    // staging reads done (barrier above); preload stages 0 and 1
    issue_chunk(0, tid, sb); CP_COMMIT();
    issue_chunk(1, tid, sb); CP_COMMIT();

    #define UPD2(s, dd, kk_) do { float _d = (dd); int _k = (kk_); \
        if (_d < s1[s]) { s2[s] = s1[s]; s1[s] = _d; k1[s] = _k; } \
        else if (_d < s2[s]) { s2[s] = _d; } } while (0)

    for (int i = 0; i < 32; i++) {
        if (i < 31) CP_WAIT(1); else CP_WAIT(0);
        __syncthreads();                      // stage i visible; iter i-1 reads done
        if (i + 2 < 32) { issue_chunk(i + 2, tid, sb); CP_COMMIT(); }
        const int cofs = (i & 3) * 8;         // A ku-offset of this 64-wide chunk
        const uint32_t bufb = sb + SM_BBUF + (uint32_t)((i % 3) * 16384);
        #pragma unroll
        for (int k16 = 0; k16 < 4; k16++) {
            uint32_t bfr[2][4];
            #pragma unroll
            for (int np = 0; np < 2; np++) {
                int nrow = wn * 32 + np * 16 + (g4 >> 1) * 8 + (lane & 7);
                int kuB = k16 * 2 + (g4 & 1);
                ldsm4(bfr[np], bufb + (uint32_t)nrow * 128u +
                               (uint32_t)((kuB ^ (nrow & 7)) << 4));
            }
            #pragma unroll
            for (int mt = 0; mt < 4; mt++) {
                int arow = wm * 64 + mt * 16 + (g4 & 1) * 8 + (lane & 7);
                int kuA = cofs + k16 * 2 + (g4 >> 1);
                uint32_t afr[4];
                ldsm4(afr, sb + (uint32_t)arow * 512u +
                           (uint32_t)((kuA ^ (arow & 7)) << 4));
                #pragma unroll
                for (int nt = 0; nt < 4; nt++)
                    mma16816(acc[mt][nt], afr, &bfr[nt >> 1][(nt & 1) * 2]);
            }
        }
        if ((i & 3) == 3) {
            int tile = i >> 2;
            #pragma unroll
            for (int mt = 0; mt < 4; mt++) {
                float zn0 = zns[wm * 64 + mt * 16 + (lane >> 2)];
                float zn1 = zns[wm * 64 + mt * 16 + 8 + (lane >> 2)];
                #pragma unroll
                for (int nt = 0; nt < 4; nt++) {
                    int c0 = wn * 32 + nt * 8 + (lane & 3) * 2;
                    int kg = tile * 128 + c0;
                    float cn0 = __ldg(&g_cnorm[kg]);
                    float cn1 = __ldg(&g_cnorm[kg + 1]);
                    UPD2(mt * 2,     zn0 + cn0 - 2.f * acc[mt][nt][0], kg);
                    UPD2(mt * 2,     zn0 + cn1 - 2.f * acc[mt][nt][1], kg + 1);
                    UPD2(mt * 2 + 1, zn1 + cn0 - 2.f * acc[mt][nt][2], kg);
                    UPD2(mt * 2 + 1, zn1 + cn1 - 2.f * acc[mt][nt][3], kg + 1);
                    acc[mt][nt][0] = acc[mt][nt][1] = acc[mt][nt][2] = acc[mt][nt][3] = 0.f;
                }
            }
        }
    }

    // quad merge (top-2 with k-tiebreak on best)
    #pragma unroll
    for (int s = 0; s < 8; s++) {
        #pragma unroll
        for (int off = 1; off <= 2; off <<= 1) {
            float ob1 = __shfl_xor_sync(0xffffffffu, s1[s], off);
            float ob2 = __shfl_xor_sync(0xffffffffu, s2[s], off);
            int   ok1 = __shfl_xor_sync(0xffffffffu, k1[s], off);
            if (ob1 < s1[s] || (ob1 == s1[s] && ok1 < k1[s])) {
                s2[s] = (s1[s] < ob2) ? s1[s] : ob2;
                s1[s] = ob1; k1[s] = ok1;
            } else {
                s2[s] = (s2[s] < ob1) ? s2[s] : ob1;
            }
        }
    }
    __syncthreads();                       // B stages dead; reuse as reduction
    float* rB1 = (float*)(smem + SM_BBUF);
    float* rB2 = rB1 + 512;
    int*   rK1 = (int*)(rB2 + 512);
    int*   Ks  = rK1 + 512;                // [128]
    float* lred = (float*)(Ks + 128);      // [4]
    if ((lane & 3) == 0) {
        #pragma unroll
        for (int s = 0; s < 8; s++) {
            int row = wm * 64 + (s >> 1) * 16 + (s & 1) * 8 + (lane >> 2);
            rB1[row * 4 + wn] = s1[s]; rB2[row * 4 + wn] = s2[s];
            rK1[row * 4 + wn] = k1[s];
        }
    }
    __syncthreads();
    if (tid < 128) {
        float B1 = rB1[tid * 4], B2 = rB2[tid * 4];
        int K1 = rK1[tid * 4];
        #pragma unroll
        for (int wq = 1; wq < 4; wq++) {
            float ob1 = rB1[tid * 4 + wq], ob2 = rB2[tid * 4 + wq];
            int   ok1 = rK1[tid * 4 + wq];
            if (ob1 < B1 || (ob1 == B1 && ok1 < K1)) {
                B2 = (B1 < ob2) ? B1 : ob2;
                B1 = ob1; K1 = ok1;
            } else {
                B2 = (B2 < ob1) ? B2 : ob1;
            }
        }
        int q = n0 + tid;
        g_idx[q] = K1;
        g_bestd[q] = B1;
        Ks[tid] = K1;
        if (B2 - B1 < MARGIN_T) {
            int pos = atomicAdd(&g_cnt, 1);
            g_list[pos] = q;
        }
        if (writeIdxF) outIdxF[q] = (float)K1;
        // loss partial: warp-reduce B1 (warps 0-3 hold 32 queries each)
        float ls = B1;
        #pragma unroll
        for (int o = 16; o > 0; o >>= 1) ls += __shfl_down_sync(0xffffffffu, ls, o);
        if (lane == 0) lred[warp] = ls;
    }
    __syncthreads();
    if (tid == 0)
        atomicAdd(&g_losssum, (double)(lred[0] + lred[1] + lred[2] + lred[3]));

    // ---- fused zq writer: thread owns (q = tid&127, ch = tid>>7) ----
    // Gather from TRANSPOSED codebook: for fixed channel row (4KB) the 32
    // random-k lane reads hit one L1-resident row; rows stream sequentially.
    {
        const int q = tid & 127, ch = tid >> 7;
        const int k = Ks[q];
        float* dst = out + (size_t)bIdx * (CC * HWD) + (size_t)ch * HWD + hw0 + q;
        #pragma unroll 8
        for (int e = 0; e < 128; e++)
            dst[(size_t)e * 2 * HWD] = __ldg(&g_cbT[(size_t)(2 * e + ch) * KK + k]);
    }
}

// ---------------- compacted exact fp32 rescue + fixups ----------------
__global__ void rescue_exact(const float* __restrict__ z, const float* __restrict__ cb,
                             float* __restrict__ out,
                             float* __restrict__ outIdxF, int writeIdxF) {
    __shared__ float cns[KK];
    __shared__ float As[8][256];
    __shared__ float znq[8];
    __shared__ int   qlist[8];
    __shared__ int   rewk[8];
    __shared__ float wred_d[8][8];
    __shared__ int   wred_k[8][8];
    const int t = threadIdx.x;
    const int lane = t & 31, w = t >> 5;
    for (int i = t; i < KK; i += 256) cns[i] = g_cnorm[i];

    for (int base = blockIdx.x * 8; base < g_cnt; base += gridDim.x * 8) {
        int nq = g_cnt - base; if (nq > 8) nq = 8;
        __syncthreads();
        if (t < 8) {
            int q = (t < nq) ? g_list[base + t] : -1;
            qlist[t] = q;
            znq[t] = (q >= 0) ? g_znorm[q] : 0.f;
            rewk[t] = -1;
        }
        __syncthreads();
        {
            int q = qlist[w];
            if (q >= 0) {
                int b = q >> 12, hw = q & 4095;
                const float* zb = z + (size_t)b * CC * HWD + hw;
                for (int c = lane; c < 256; c += 32) As[w][c] = zb[(size_t)c * HWD];
            }
        }
        __syncthreads();

        float acc[8][4];
        #pragma unroll
        for (int qj = 0; qj < 8; qj++)
            #pragma unroll
            for (int j = 0; j < 4; j++) acc[qj][j] = 0.f;

        const float4* cbt4 = (const float4*)g_cbT;
        for (int c = 0; c < 256; c++) {
            float4 cb4 = cbt4[c * 256 + t];
            #pragma unroll
            for (int qj = 0; qj < 8; qj++) {
                float zv = As[qj][c];
                acc[qj][0] = fmaf(zv, cb4.x, acc[qj][0]);
                acc[qj][1] = fmaf(zv, cb4.y, acc[qj][1]);
                acc[qj][2] = fmaf(zv, cb4.z, acc[qj][2]);
                acc[qj][3] = fmaf(zv, cb4.w, acc[qj][3]);
            }
        }

        #pragma unroll
        for (int qj = 0; qj < 8; qj++) {
            float bd = 3.4e38f; int bk = 0;
            #pragma unroll
            for (int j = 0; j < 4; j++) {
                int k = t * 4 + j;
                float d = (znq[qj] + cns[k]) - 2.f * acc[qj][j];
                if (d < bd) { bd = d; bk = k; }
            }
            #pragma unroll
            for (int off = 16; off > 0; off >>= 1) {
                float od = __shfl_down_sync(0xffffffffu, bd, off);
                int   ok = __shfl_down_sync(0xffffffffu, bk, off);
                if (od < bd || (od == bd && ok < bk)) { bd = od; bk = ok; }
            }
            if (lane == 0) { wred_d[qj][w] = bd; wred_k[qj][w] = bk; }
        }
        __syncthreads();
        if (t < nq) {
            float bd = wred_d[t][0]; int bk = wred_k[t][0];
            #pragma unroll
            for (int w2 = 1; w2 < 8; w2++) {
                float od = wred_d[t][w2]; int ok = wred_k[t][w2];
                if (od < bd || (od == bd && ok < bk)) { bd = od; bk = ok; }
            }
            int q = qlist[t];
            int oldk = g_idx[q];
            atomicAdd(&g_losssum, (double)(bd - g_bestd[q]));
            g_idx[q] = bk;
            g_bestd[q] = bd;
            if (bk != oldk) rewk[t] = bk;
            if (writeIdxF) outIdxF[q] = (float)bk;
        }
        __syncthreads();
        // rewrite zq rows whose index changed (one c per thread)
        for (int j = 0; j < nq; j++) {
            int bkj = rewk[j];
            if (bkj >= 0) {
                int q = qlist[j];
                int b = q >> 12, hw = q & 4095;
                out[(size_t)b * (CC * HWD) + (size_t)t * HWD + hw] =
                    __ldg(&cb[(size_t)bkj * CC + t]);
            }
        }
        __syncthreads();
    }
}

// ---------------- loss finalize ----------------
__global__ void loss_finalize(float* __restrict__ outLoss) {
    double m = g_losssum / (double)ZQ_ELEMS;
    float mf = (float)m;
    *outLoss = mf - 0.25f * mf;
}

// ---------------- launch ----------------
extern "C" void kernel_launch(void* const* d_in, const int* in_sizes, int n_in,
                              void* d_out, int out_size) {
    const float* z  = (const float*)d_in[0];
    const float* cb = (const float*)d_in[1];
    if (n_in >= 2 && in_sizes[0] == KK * CC && in_sizes[1] == (int)ZQ_ELEMS) {
        z = (const float*)d_in[1]; cb = (const float*)d_in[0];
    }
    float* out = (float*)d_out;

    cudaFuncSetAttribute(vq_tc, cudaFuncAttributeMaxDynamicSharedMemorySize, SM_TOT);

    int writeIdxF = (out_size >= (int)(ZQ_ELEMS + NQ)) ? 1 : 0;
    float* outIdxF = out + ZQ_ELEMS;

    // launch order: vq_tc must stay the 4th launch (ncu profiles launch #4)
    prep_cbA<<<1024, 256>>>(cb);                                   // 1
    prep_cbB<<<4, 256>>>(cb);                                      // 2
    zero_state<<<1, 1>>>();                                        // 3
    vq_tc<<<NQ / 128, 256, SM_TOT>>>(z, cb, out, outIdxF, writeIdxF); // 4 <- profiled
    rescue_exact<<<256, 256>>>(z, cb, out, outIdxF, writeIdxF);    // 5
    if (out_size >= (int)(ZQ_ELEMS + NQ + 1)) {
        loss_finalize<<<1, 1>>>(out + ZQ_ELEMS + NQ);              // 6
    }
}